// round 17
// baseline (speedup 1.0000x reference)
#include <cuda_runtime.h>
#include <math.h>

#define NA   512
#define OBSD 128
#define INP  656
#define HID  64
#define LAT  256
#define NH   64
#define LOG2PI 1.8378770664093453f
#define BNEPS 1e-5f

typedef unsigned long long ull;

// ---------------- scratch (device globals; no allocation allowed) ----------------
// g_A/g_B/g_Ac/g_Bc/g_w1 are TRANSPOSED: [c][s] i.e. index c*NA + s
__device__ __align__(16) float g_pre_e[NA*NH];
__device__ __align__(16) float g_pre_i[NA*NH];
__device__ float g_bnsum[2][NH], g_bnsq[2][NH];     // BN column stats (atomic; reset by k_sums tail)
__device__ __align__(16) float g_mu[NA*LAT];
__device__ __align__(16) float g_ni2v[NA*LAT], g_cc[NA*LAT], g_lat[NA*LAT];
__device__ __align__(16) float g_A[NH*NA], g_B[NH*NA];
__device__ __align__(16) float g_Ac[NH*NA], g_Bc[NH*NA];
__device__ __align__(16) float g_w1[NH*NA];
__device__ float g_csA[NH], g_csB[NH], g_csS[NH];   // A/B column stats (atomic)
__device__ __align__(16) float g_mi[NA*NA], g_dis[NA*NA];
__device__ double g_ent, g_kl, g_sum_disn, g_sum_min;
__device__ unsigned g_keymin[2], g_keymax[2];
__device__ unsigned g_done;

// ordered-uint encoding for float atomic min/max
__device__ __forceinline__ unsigned fkey(float f) {
    unsigned u = __float_as_uint(f);
    return (u & 0x80000000u) ? ~u : (u | 0x80000000u);
}
__device__ __forceinline__ float funkey(unsigned k) {
    unsigned u = (k & 0x80000000u) ? (k & 0x7fffffffu) : ~k;
    return __uint_as_float(u);
}

// ---- packed f32x2 helpers (sm_103a; only add/mul/fma exist packed) ----
__device__ __forceinline__ ull p2_add(ull a, ull b) {
    ull r; asm("add.rn.f32x2 %0,%1,%2;" : "=l"(r) : "l"(a), "l"(b)); return r;
}
__device__ __forceinline__ ull p2_mul(ull a, ull b) {
    ull r; asm("mul.rn.f32x2 %0,%1,%2;" : "=l"(r) : "l"(a), "l"(b)); return r;
}
__device__ __forceinline__ ull p2_fma(ull a, ull b, ull c) {
    ull r; asm("fma.rn.f32x2 %0,%1,%2,%3;" : "=l"(r) : "l"(a), "l"(b), "l"(c)); return r;
}
__device__ __forceinline__ ull p2_pack(float lo, float hi) {
    ull r; asm("mov.b64 %0,{%1,%2};" : "=l"(r) : "f"(lo), "f"(hi)); return r;
}
__device__ __forceinline__ float p2_lo(ull a) { return __uint_as_float((unsigned)a); }
__device__ __forceinline__ float p2_hi(ull a) { return __uint_as_float((unsigned)(a >> 32)); }
__device__ __forceinline__ ull lds_b64(const float* p) {
    return __double_as_longlong(*(const double*)p);
}

// ---------------- fused linear1 + BN column stats (encoder: 1 row/block; inference: 2 rows/block) ----------------
__global__ void k_lin(const float* __restrict__ obs, const float* __restrict__ hid,
                      const float* __restrict__ eW1, const float* __restrict__ eb1,
                      const float* __restrict__ iW1, const float* __restrict__ ib1) {
    int b = blockIdx.x, t = threadIdx.x;   // 768 blocks, 128 threads
    if (b == 0) {
        if (t == 0) {
            g_ent = 0.0; g_kl = 0.0; g_sum_disn = 0.0; g_sum_min = 0.0;
            g_keymin[0] = 0xFFFFFFFFu; g_keymin[1] = 0xFFFFFFFFu;
            g_keymax[0] = 0u; g_keymax[1] = 0u;
            g_done = 0u;
        }
        if (t < NH) { g_csA[t] = 0.f; g_csB[t] = 0.f; g_csS[t] = 0.f; }
    }
    __shared__ float s[2][HID + INP];
    __shared__ float part[8][2][NH];
    int g = t & 15, hh = t >> 4;   // 16 col-groups x 8 l-slices
    int c0 = g * 4;
    if (b < NA) {
        int i = b;
        if (t < 32) ((float4*)&s[0][0])[t] = *(const float4*)(obs + i*INP + (INP-OBSD) + 4*t);
        __syncthreads();
        float4 acc = make_float4(0.f, 0.f, 0.f, 0.f);
        int l0 = hh * 16;
        #pragma unroll 16
        for (int l = l0; l < l0 + 16; l++) {
            float4 w = *(const float4*)&eW1[l*NH + c0];
            float x = s[0][l];
            acc.x = fmaf(x, w.x, acc.x); acc.y = fmaf(x, w.y, acc.y);
            acc.z = fmaf(x, w.z, acc.z); acc.w = fmaf(x, w.w, acc.w);
        }
        part[hh][0][c0+0] = acc.x; part[hh][0][c0+1] = acc.y;
        part[hh][0][c0+2] = acc.z; part[hh][0][c0+3] = acc.w;
        __syncthreads();
        if (t < NH) {
            float r = eb1[t];
            #pragma unroll
            for (int k = 0; k < 8; k++) r += part[k][0][t];
            g_pre_e[i*NH + t] = r;
            atomicAdd(&g_bnsum[0][t], r);
            atomicAdd(&g_bnsq[0][t], r*r);
        }
    } else {
        int i0 = (b - NA) * 2;
        for (int idx = t; idx < 360; idx += 128) {
            int r = idx / 180, q = idx % 180;
            float4 v;
            if (q < 16) v = ((const float4*)(hid + (i0+r)*HID))[q];
            else        v = ((const float4*)(obs + (i0+r)*INP))[q - 16];
            ((float4*)&s[r][0])[q] = v;
        }
        __syncthreads();
        float4 a0 = make_float4(0.f,0.f,0.f,0.f), a1 = make_float4(0.f,0.f,0.f,0.f);
        int l0 = hh * 90;
        #pragma unroll 10
        for (int l = l0; l < l0 + 90; l++) {
            float4 w = *(const float4*)&iW1[l*NH + c0];
            float x0 = s[0][l], x1 = s[1][l];
            a0.x = fmaf(x0, w.x, a0.x); a0.y = fmaf(x0, w.y, a0.y);
            a0.z = fmaf(x0, w.z, a0.z); a0.w = fmaf(x0, w.w, a0.w);
            a1.x = fmaf(x1, w.x, a1.x); a1.y = fmaf(x1, w.y, a1.y);
            a1.z = fmaf(x1, w.z, a1.z); a1.w = fmaf(x1, w.w, a1.w);
        }
        part[hh][0][c0+0] = a0.x; part[hh][0][c0+1] = a0.y;
        part[hh][0][c0+2] = a0.z; part[hh][0][c0+3] = a0.w;
        part[hh][1][c0+0] = a1.x; part[hh][1][c0+1] = a1.y;
        part[hh][1][c0+2] = a1.z; part[hh][1][c0+3] = a1.w;
        __syncthreads();
        if (t < 128) {
            int gg = t >> 6, c = t & 63;
            float r = ib1[c];
            #pragma unroll
            for (int k = 0; k < 8; k++) r += part[k][gg][c];
            g_pre_i[(i0+gg)*NH + c] = r;
            atomicAdd(&g_bnsum[1][c], r);
            atomicAdd(&g_bnsq[1][c], r*r);
        }
    }
}

// ---------------- fused: BN apply + enc/inf linear2 + latent head + entropy + KL + A/B GEMV + col stats ----------------
// 256 blocks x 256 threads, 2 rows/block. Thread roles:
//   t in [0,64):    encoder, cols 4t..4t+3        (mu region)
//   t in [64,128):  encoder, cols 4t..4t+3        (logvar region)
//   t in [128,192): inference, cols 4(t-128)..+3  (mu region)
//   t in [192,256): inference, cols 4(t-128)..+3  (logvar region)
__global__ void k_lat(const float* __restrict__ eW2, const float* __restrict__ eb2,
                      const float* __restrict__ iW2, const float* __restrict__ ib2,
                      const float* __restrict__ eps, const float* __restrict__ dW1,
                      const float* __restrict__ eg, const float* __restrict__ ebt,
                      const float* __restrict__ ig, const float* __restrict__ ibt) {
    int i0 = blockIdx.x * 2, t = threadIdx.x;
    __shared__ float sscale[2][NH], sshift[2][NH];
    __shared__ float he[2][NH], hif[2][NH];
    __shared__ float sMuE[2][LAT], sMuI[2][LAT];
    __shared__ float sVarE[2][LAT], sLsE[2][LAT];
    __shared__ float sLat[2][LAT];
    __shared__ float red1[256], red2[256];
    __shared__ float pa[4][2][NH], pb[4][2][NH];
    // BN scale/shift from accumulated column stats
    if (t < 64) {
        float mean = g_bnsum[0][t] * (1.f/NA);
        float var  = g_bnsq[0][t] * (1.f/NA) - mean*mean;
        float sc = eg[t] * rsqrtf(var + BNEPS);
        sscale[0][t] = sc; sshift[0][t] = ebt[t] - mean*sc;
    } else if (t >= 128 && t < 192) {
        int c = t - 128;
        float mean = g_bnsum[1][c] * (1.f/NA);
        float var  = g_bnsq[1][c] * (1.f/NA) - mean*mean;
        float sc = ig[c] * rsqrtf(var + BNEPS);
        sscale[1][c] = sc; sshift[1][c] = ibt[c] - mean*sc;
    }
    __syncthreads();
    {
        int g = (t >> 6) & 1, c = t & 63;
        if (t < 128) {
            float x = fmaf(g_pre_e[(i0+g)*NH + c], sscale[0][c], sshift[0][c]);
            he[g][c] = (x > 0.f) ? x : 0.01f*x;
        } else {
            float x = fmaf(g_pre_i[(i0+g)*NH + c], sscale[1][c], sshift[1][c]);
            hif[g][c] = (x > 0.f) ? x : 0.01f*x;
        }
    }
    __syncthreads();
    const bool isE = (t < 128);
    const int c0 = isE ? 4*t : 4*(t-128);           // column base within 2*LAT
    const float* __restrict__ W = isE ? eW2 : iW2;
    const float* __restrict__ Bv = isE ? eb2 : ib2;
    float4 bq = *(const float4*)&Bv[c0];
    float4 a0 = bq, a1 = bq;                         // rows g=0,1
    {
        const float (*h)[NH] = isE ? he : hif;
        #pragma unroll 8
        for (int l = 0; l < NH; l++) {
            float4 w = *(const float4*)&W[l*(2*LAT) + c0];
            float h0 = h[0][l], h1 = h[1][l];
            a0.x = fmaf(h0, w.x, a0.x); a0.y = fmaf(h0, w.y, a0.y);
            a0.z = fmaf(h0, w.z, a0.z); a0.w = fmaf(h0, w.w, a0.w);
            a1.x = fmaf(h1, w.x, a1.x); a1.y = fmaf(h1, w.y, a1.y);
            a1.z = fmaf(h1, w.z, a1.z); a1.w = fmaf(h1, w.w, a1.w);
        }
    }
    // phase 2: stash mu
    if (t < 64) {
        *(float4*)&sMuE[0][c0] = a0;
        *(float4*)&sMuE[1][c0] = a1;
        *(float4*)&g_mu[i0*LAT + c0]     = a0;
        *(float4*)&g_mu[(i0+1)*LAT + c0] = a1;
    } else if (t >= 128 && t < 192) {
        *(float4*)&sMuI[0][c0] = a0;
        *(float4*)&sMuI[1][c0] = a1;
    }
    float ent = 0.f, kl = 0.f;
    // encoder logvar threads: head stats (no mu needed yet)
    if (isE && t >= 64) {
        const int li = c0 - LAT;   // [0,252]
        float lv[2][4] = {{a0.x,a0.y,a0.z,a0.w},{a1.x,a1.y,a1.z,a1.w}};
        #pragma unroll
        for (int g = 0; g < 2; g++) {
            float4 vv, ls, ni, cc;
            float* vvp = (float*)&vv; float* lsp = (float*)&ls;
            float* nip = (float*)&ni; float* ccp = (float*)&cc;
            #pragma unroll
            for (int k = 0; k < 4; k++) {
                float v = fmaxf(expf(lv[g][k]), 0.002f);
                float l = 0.5f*logf(v);
                vvp[k] = v; lsp[k] = l;
                nip[k] = -0.5f/v;
                ccp[k] = 13.9f - l - 0.5f*LOG2PI;
                ent += 0.5f + 0.5f*LOG2PI + l;
            }
            int gi = (i0+g)*LAT + li;
            *(float4*)&g_ni2v[gi] = ni;
            *(float4*)&g_cc[gi]   = cc;
            *(float4*)&sVarE[g][li] = vv;
            *(float4*)&sLsE[g][li]  = ls;
        }
    }
    __syncthreads();
    // phase 3: latent (needs mu) + KL (needs var/ls/muE/muI)
    if (isE && t >= 64) {
        const int li = c0 - LAT;
        #pragma unroll
        for (int g = 0; g < 2; g++) {
            int gi = (i0+g)*LAT + li;
            float4 mu = *(const float4*)&sMuE[g][li];
            float4 vv = *(const float4*)&sVarE[g][li];
            float4 e4 = *(const float4*)&eps[gi];
            float4 lt;
            lt.x = fmaf(sqrtf(vv.x), e4.x, mu.x);
            lt.y = fmaf(sqrtf(vv.y), e4.y, mu.y);
            lt.z = fmaf(sqrtf(vv.z), e4.z, mu.z);
            lt.w = fmaf(sqrtf(vv.w), e4.w, mu.w);
            *(float4*)&g_lat[gi] = lt;
            *(float4*)&sLat[g][li] = lt;
        }
    } else if (!isE && t >= 192) {
        const int li = c0 - LAT;
        float lv[2][4] = {{a0.x,a0.y,a0.z,a0.w},{a1.x,a1.y,a1.z,a1.w}};
        #pragma unroll
        for (int g = 0; g < 2; g++) {
            float4 mu  = *(const float4*)&sMuE[g][li];
            float4 muq = *(const float4*)&sMuI[g][li];
            float4 vv  = *(const float4*)&sVarE[g][li];
            float4 ls  = *(const float4*)&sLsE[g][li];
            const float* mup = (const float*)&mu; const float* muqp = (const float*)&muq;
            const float* vvp = (const float*)&vv; const float* lsp = (const float*)&ls;
            #pragma unroll
            for (int k = 0; k < 4; k++) {
                float vq = fmaxf(expf(lv[g][k]), 0.002f);
                float lsq = 0.5f*logf(vq);
                float d = mup[k] - muqp[k];
                kl += lsq - lsp[k] + (vvp[k] + d*d) / (2.f*vq) - 0.5f;
            }
        }
    }
    red1[t] = ent; red2[t] = kl;
    __syncthreads();
    for (int o = 128; o; o >>= 1) {
        if (t < o) { red1[t] += red1[t+o]; red2[t] += red2[t+o]; }
        __syncthreads();
    }
    if (t == 0) { atomicAdd(&g_ent, (double)red1[0]); atomicAdd(&g_kl, (double)red2[0]); }
    __syncthreads();
    // ---- A/B GEMV on the latent already in smem ----
    const int c = t & 63, q = t >> 6;
    float b0 = 0.f, b1 = 0.f, aa0 = 0.f, aa1 = 0.f;
    const int l0 = q * 64;
    #pragma unroll 8
    for (int l = l0; l < l0 + 64; l++) {
        float wa = dW1[l*NH + c];
        float wb = dW1[(l + LAT)*NH + c];
        float L0 = sLat[0][l], L1 = sLat[1][l];
        aa0 = fmaf(L0, wa, aa0); b0 = fmaf(L0, wb, b0);
        aa1 = fmaf(L1, wa, aa1); b1 = fmaf(L1, wb, b1);
    }
    pa[q][0][c] = aa0; pa[q][1][c] = aa1;
    pb[q][0][c] = b0; pb[q][1][c] = b1;
    __syncthreads();
    if (t < 128) {
        int g = t >> 6, c2 = t & 63;
        float av = pa[0][g][c2] + pa[1][g][c2] + pa[2][g][c2] + pa[3][g][c2];
        float bv = pb[0][g][c2] + pb[1][g][c2] + pb[2][g][c2] + pb[3][g][c2];
        g_A[c2*NA + i0+g] = av;
        g_B[c2*NA + i0+g] = bv;
        atomicAdd(&g_csA[c2], av);
        atomicAdd(&g_csB[c2], bv);
        atomicAdd(&g_csS[c2], av*av + bv*bv);
    }
}

// ---------------- fused: center (to g_Ac/g_Bc) + circ-corr -> w1 (stats precomputed) ----------------
// grid (64 columns, 2 s-halves), 512 threads; float2 conflict-free correlation loop
__global__ void k_col(const float* __restrict__ dg) {
    int c = blockIdx.x, sh = blockIdx.y;
    int t = threadIdx.x;
    __shared__ float a[NA], b2[2*NA];
    __shared__ float part0[512], part1[512];
    float mA = g_csA[c] * (1.f/NA);
    float mB = g_csB[c] * (1.f/NA);
    float s2 = g_csS[c] * (1.f/NA) - mA*mA - mB*mB;
    float av = g_A[c*NA + t] - mA, bv = g_B[c*NA + t] - mB;
    a[t] = av; b2[t] = bv; b2[t + NA] = bv;
    if (sh == 0) { g_Ac[c*NA + t] = av; g_Bc[c*NA + t] = bv; }
    __syncthreads();
    const int sq = t & 127, jh = t >> 7;
    const int s0 = sh*256 + 2*sq;
    const int jbase = jh * 128;
    const float2* ap2 = (const float2*)&a[jbase];
    const float2* bp2 = (const float2*)&b2[510 - s0 + jbase];
    float cr0 = 0.f, cr1 = 0.f;
    float2 cur = bp2[0];
    #pragma unroll 8
    for (int k = 0; k < 64; k++) {
        float2 nxt = bp2[k + 1];
        float2 a2 = ap2[k];
        cr1 = fmaf(a2.x, cur.x, cr1);
        cr0 = fmaf(a2.x, cur.y, cr0);
        cr1 = fmaf(a2.y, cur.y, cr1);
        cr0 = fmaf(a2.y, nxt.x, cr0);
        cur = nxt;
    }
    part0[t] = cr0; part1[t] = cr1;
    __syncthreads();
    if (t < 128) {
        float c0 = part0[t] + part0[t+128] + part0[t+256] + part0[t+384];
        float c1 = part1[t] + part1[t+128] + part1[t+256] + part1[t+384];
        int ss0 = sh*256 + 2*t;
        float var0 = s2 + 2.f * c0 * (1.f/NA);
        float var1 = s2 + 2.f * c1 * (1.f/NA);
        float scale = dg[c];
        *(float2*)&g_w1[c*NA + ss0] = make_float2(scale * rsqrtf(var0 + BNEPS),
                                                  scale * rsqrtf(var1 + BNEPS));
    }
}

// ---------------- fused MI (z=0) + DIS (z=1): 32j x 64s tiles, 2jx4s per thread ----------------
// grid dim3(16, 8, 2), 256 threads
__global__ void k_midis(const float* __restrict__ dbt,
                        const float* __restrict__ dW2,
                        const float* __restrict__ db2) {
    __shared__ float sh[6528];
    const int tid = threadIdx.x;            // 256
    const int j0 = blockIdx.x * 32, s0 = blockIdx.y * 64;
    const int tx = tid & 15, ty = tid >> 4;
    const int jj0 = 2*tx, ss0 = 4*ty;
    const int base = (j0 - s0 - 64) & (NA-1);
    const int w0 = jj0 - ss0 + 60;          // even, in [0,90]; window rows w0..w0+5
    float vmn, vmx;
    if (blockIdx.z == 0) {
        // ---- MI: packed f32x2 over the j-pair, scalar max ----
        float* sNM = sh;            // [32 l][34]  (-mu)
        float* sNI = sh + 1088;     // [32 l][34]
        float* sCC = sh + 2176;     // [32 l][34]
        float* sL  = sh + 3264;     // [32 l][98]  (96 rows + pad)
        float accL[4] = {0.f,0.f,0.f,0.f}, accH[4] = {0.f,0.f,0.f,0.f};
        for (int l0 = 0; l0 < LAT; l0 += 32) {
            #pragma unroll
            for (int i = 0; i < 4; i++) {
                int idx = tid + i*256;
                int jj = idx >> 5, lc = idx & 31;
                int g = (j0 + jj)*LAT + l0 + lc;
                sNM[lc*34 + jj] = -g_mu[g];
                sNI[lc*34 + jj] = g_ni2v[g];
                sCC[lc*34 + jj] = g_cc[g];
            }
            #pragma unroll
            for (int i = 0; i < 12; i++) {
                int idx = tid + i*256;
                int rr = idx >> 5, lc = idx & 31;
                sL[lc*98 + rr] = g_lat[((base + rr) & (NA-1))*LAT + l0 + lc];
            }
            __syncthreads();
            #pragma unroll
            for (int l = 0; l < 32; l++) {
                ull nm2 = lds_b64(&sNM[l*34 + jj0]);
                ull ni2 = lds_b64(&sNI[l*34 + jj0]);
                ull cc2 = lds_b64(&sCC[l*34 + jj0]);
                float2 L01 = *(const float2*)&sL[l*98 + w0];
                float2 L23 = *(const float2*)&sL[l*98 + w0 + 2];
                float2 L45 = *(const float2*)&sL[l*98 + w0 + 4];
                ull P[4];
                P[0] = p2_pack(L23.y, L45.x);   // a=0: (3,4)
                P[1] = p2_pack(L23.x, L23.y);   // a=1: (2,3)
                P[2] = p2_pack(L01.y, L23.x);   // a=2: (1,2)
                P[3] = p2_pack(L01.x, L01.y);   // a=3: (0,1)
                #pragma unroll
                for (int a = 0; a < 4; a++) {
                    ull d = p2_add(P[a], nm2);
                    ull q = p2_mul(d, d);
                    ull r = p2_fma(q, ni2, cc2);
                    accL[a] += fmaxf(p2_lo(r), -13.9f);
                    accH[a] += fmaxf(p2_hi(r), -13.9f);
                }
            }
            __syncthreads();
        }
        const float inv = 1.f / LAT;
        float o[4][2];
        #pragma unroll
        for (int a = 0; a < 4; a++) {
            o[a][0] = accL[a]*inv; o[a][1] = accH[a]*inv;
            *(float2*)&g_mi[(s0+ss0+a)*NA + j0+jj0] = make_float2(o[a][0], o[a][1]);
        }
        vmn = o[0][0]; vmx = o[0][0];
        #pragma unroll
        for (int a = 0; a < 4; a++) {
            vmn = fminf(vmn, fminf(o[a][0], o[a][1]));
            vmx = fmaxf(vmx, fmaxf(o[a][0], o[a][1]));
        }
    } else {
        // ---- DIS: scalar, c-chunked (2 chunks of 32) ----
        float* sa   = sh;            // [32 c][34]
        float* sw   = sh + 1088;     // [32 c][68]
        float* sb   = sh + 3264;     // [32 c][98]
        float* sdbt = sh + 6400;     // 64
        float* sdw2 = sh + 6464;     // 64
        if (tid < NH) { sdbt[tid] = dbt[tid]; sdw2[tid] = dW2[tid]; }
        float acc[4][2] = {{0.f,0.f},{0.f,0.f},{0.f,0.f},{0.f,0.f}};
        for (int cb = 0; cb < NH; cb += 32) {
            #pragma unroll
            for (int i = 0; i < 4; i++) {
                int idx = tid + i*256;
                int cc = idx >> 5, jj = idx & 31;
                sa[cc*34 + jj] = g_Ac[(cb+cc)*NA + j0 + jj];
            }
            #pragma unroll
            for (int i = 0; i < 8; i++) {
                int idx = tid + i*256;
                int cc = idx >> 6, ss = idx & 63;
                sw[cc*68 + ss] = g_w1[(cb+cc)*NA + s0 + ss];
            }
            #pragma unroll
            for (int i = 0; i < 16; i++) {
                int idx = tid + i*256;
                int cc = idx >> 7, rr = idx & 127;
                if (rr < 96)
                    sb[cc*98 + rr] = g_Bc[(cb+cc)*NA + ((base + rr) & (NA-1))];
            }
            __syncthreads();
            #pragma unroll 4
            for (int cc = 0; cc < 32; cc++) {
                float2 a2 = *(const float2*)&sa[cc*34 + jj0];
                float4 w4 = *(const float4*)&sw[cc*68 + ss0];
                float2 B01 = *(const float2*)&sb[cc*98 + w0];
                float2 B23 = *(const float2*)&sb[cc*98 + w0 + 2];
                float2 B45 = *(const float2*)&sb[cc*98 + w0 + 4];
                float Bw[5] = {B01.x, B01.y, B23.x, B23.y, B45.x};
                float bt = sdbt[cb+cc], w2 = sdw2[cb+cc];
                float wa[4] = {w4.x, w4.y, w4.z, w4.w};
                float aj[2] = {a2.x, a2.y};
                #pragma unroll
                for (int a = 0; a < 4; a++) {
                    #pragma unroll
                    for (int bb = 0; bb < 2; bb++) {
                        float u = fmaf(aj[bb] + Bw[3 + bb - a], wa[a], bt);
                        u = fmaxf(u, 0.01f*u);   // leaky relu
                        acc[a][bb] = fmaf(u, w2, acc[a][bb]);
                    }
                }
            }
            __syncthreads();
        }
        float b2v = db2[0];
        float o[4][2];
        #pragma unroll
        for (int a = 0; a < 4; a++) {
            o[a][0] = fabsf(acc[a][0] + b2v);
            o[a][1] = fabsf(acc[a][1] + b2v);
            *(float2*)&g_dis[(s0+ss0+a)*NA + j0+jj0] = make_float2(o[a][0], o[a][1]);
        }
        vmn = o[0][0]; vmx = o[0][0];
        #pragma unroll
        for (int a = 0; a < 4; a++) {
            vmn = fminf(vmn, fminf(o[a][0], o[a][1]));
            vmx = fmaxf(vmx, fmaxf(o[a][0], o[a][1]));
        }
    }
    // ---- block min/max -> global atomic keys ----
    #pragma unroll
    for (int o2 = 16; o2; o2 >>= 1) {
        vmn = fminf(vmn, __shfl_xor_sync(0xFFFFFFFFu, vmn, o2));
        vmx = fmaxf(vmx, __shfl_xor_sync(0xFFFFFFFFu, vmx, o2));
    }
    __shared__ float wmn[8], wmx[8];
    if ((tid & 31) == 0) { wmn[tid>>5] = vmn; wmx[tid>>5] = vmx; }
    __syncthreads();
    if (tid == 0) {
        float a = wmn[0], b = wmx[0];
        #pragma unroll
        for (int k = 1; k < 8; k++) { a = fminf(a, wmn[k]); b = fmaxf(b, wmx[k]); }
        atomicMin(&g_keymin[blockIdx.z], fkey(a));
        atomicMax(&g_keymax[blockIdx.z], fkey(b));
    }
}

// ---------------- normalized sums (float4) + last-block final assembly + accumulator reset ----------------
__global__ void k_sums(float* __restrict__ out) {
    int tid = threadIdx.x;                      // 128 blocks x 256 threads
    float mi_min = funkey(g_keymin[0]);
    float mi_inv = 1.f / (funkey(g_keymax[0]) - mi_min + 1e-12f);
    float ds_min = funkey(g_keymin[1]);
    float ds_inv = 1.f / (funkey(g_keymax[1]) - ds_min + 1e-12f);
    const float4* mi4 = (const float4*)g_mi;
    const float4* ds4 = (const float4*)g_dis;
    double s1 = 0.0, s2 = 0.0;
    #pragma unroll
    for (int i = 0; i < 2; i++) {
        int f = blockIdx.x*512 + tid + i*256;
        float4 m = mi4[f], d = ds4[f];
        float mn0 = (m.x - mi_min)*mi_inv, dn0 = (d.x - ds_min)*ds_inv;
        float mn1 = (m.y - mi_min)*mi_inv, dn1 = (d.y - ds_min)*ds_inv;
        float mn2 = (m.z - mi_min)*mi_inv, dn2 = (d.z - ds_min)*ds_inv;
        float mn3 = (m.w - mi_min)*mi_inv, dn3 = (d.w - ds_min)*ds_inv;
        s1 += (double)dn0 + (double)dn1 + (double)dn2 + (double)dn3;
        s2 += (double)fminf(mn0 + dn0, 1.0f) + (double)fminf(mn1 + dn1, 1.0f)
            + (double)fminf(mn2 + dn2, 1.0f) + (double)fminf(mn3 + dn3, 1.0f);
    }
    __shared__ double d1[256], d2[256];
    d1[tid] = s1; d2[tid] = s2;
    __syncthreads();
    for (int o = 128; o; o >>= 1) {
        if (tid < o) { d1[tid] += d1[tid+o]; d2[tid] += d2[tid+o]; }
        __syncthreads();
    }
    if (tid == 0) {
        atomicAdd(&g_sum_disn, d1[0]);
        atomicAdd(&g_sum_min, d2[0]);
        __threadfence();
        unsigned old = atomicAdd(&g_done, 1u);
        if (old == 127u) {   // last of 128 blocks
            __threadfence();
            double sum_disn = atomicAdd(&g_sum_disn, 0.0);
            double sum_min  = atomicAdd(&g_sum_min, 0.0);
            double ent = atomicAdd(&g_ent, 0.0) / (double)NA;
            double kl  = atomicAdd(&g_kl, 0.0)  / (double)NA;
            double loss0 = fmin(ent*1e-4 + kl*1e-4, 2000.0);
            double ce = log1p(exp(loss0));
            double dis_norm = sum_disn / (double)NA;
            double dis_loss = -sum_min / (double)NA;
            double cdis = (dis_norm + dis_loss) / (double)NA;
            out[0] = (float)(ce + cdis);
            out[1] = (float)cdis;
            out[2] = (float)ce;
            // reset BN accumulators for the next (graph-replayed) run;
            // zero-initialized at module load, so every run sees zeros.
            #pragma unroll
            for (int k = 0; k < NH; k++) {
                g_bnsum[0][k] = 0.f; g_bnsum[1][k] = 0.f;
                g_bnsq[0][k]  = 0.f; g_bnsq[1][k]  = 0.f;
            }
        }
    }
}

// ---------------- launcher ----------------
extern "C" void kernel_launch(void* const* d_in, const int* in_sizes, int n_in,
                              void* d_out, int out_size) {
    const float* obs  = (const float*)d_in[0];
    const float* hid  = (const float*)d_in[1];
    const float* eps  = (const float*)d_in[2];
    const float* eW1  = (const float*)d_in[3];
    const float* eb1  = (const float*)d_in[4];
    const float* eg   = (const float*)d_in[5];
    const float* ebt  = (const float*)d_in[6];
    const float* eW2  = (const float*)d_in[7];
    const float* eb2  = (const float*)d_in[8];
    const float* iW1  = (const float*)d_in[9];
    const float* ib1  = (const float*)d_in[10];
    const float* ig   = (const float*)d_in[11];
    const float* ibt  = (const float*)d_in[12];
    const float* iW2  = (const float*)d_in[13];
    const float* ib2  = (const float*)d_in[14];
    const float* dW1  = (const float*)d_in[15];
    const float* db1  = (const float*)d_in[16]; (void)db1; // cancels in BN
    const float* dg   = (const float*)d_in[17];
    const float* dbt  = (const float*)d_in[18];
    const float* dW2  = (const float*)d_in[19];
    const float* db2  = (const float*)d_in[20];
    float* out = (float*)d_out;

    k_lin<<<NA + NA/2, 128>>>(obs, hid, eW1, eb1, iW1, ib1);
    k_lat<<<256, 256>>>(eW2, eb2, iW2, ib2, eps, dW1, eg, ebt, ig, ibt);
    k_col<<<dim3(64, 2), 512>>>(dg);
    k_midis<<<dim3(16, 8, 2), 256>>>(dbt, dW2, db2);
    k_sums<<<128, 256>>>(out);
}